// round 1
// baseline (speedup 1.0000x reference)
#include <cuda_runtime.h>

// HEALPix p=1 padding: x (24,128,128,128) f32 -> y (24,128,130,130) f32
// B=2, 12 faces, C=128, n=128.
// Plane P in [0,3072): P = (b*12+F)*128 + ch. Face F = (P>>7) % 12.
// Neighbor face F' plane base delta = (F'-F)*128*16384 elements.

#define NN 128
#define NP 130
#define PLANE_IN  (NN*NN)      // 16384
#define PLANE_OUT (NP*NP)      // 16900
#define FACE_DELTA (128*PLANE_IN)  // 2097152
#define NPLANES 3072
#define NWARPS (NPLANES*NP)    // 399360

// Per-face neighbor table: t, tl, lft, bl, b, br, rgt, tr
// (tl/br unused for equatorial faces -> -1; their corners blend t/lft and b/rgt)
__constant__ int NBT[12][8] = {
    {1, 2, 3, 3, 4, 8, 5, 1},      // F0  north
    {2, 3, 0, 0, 5, 9, 6, 2},      // F1
    {3, 0, 1, 1, 6, 10, 7, 3},     // F2
    {0, 1, 2, 2, 7, 11, 4, 0},     // F3
    {0, -1, 3, 7, 11, -1, 8, 5},   // F4  equatorial
    {1, -1, 0, 4, 8, -1, 9, 6},    // F5
    {2, -1, 1, 5, 9, -1, 10, 7},   // F6
    {3, -1, 2, 6, 10, -1, 11, 4},  // F7
    {5, 0, 4, 11, 11, 10, 9, 9},   // F8  south
    {6, 1, 5, 8, 8, 11, 10, 10},   // F9
    {7, 2, 6, 9, 9, 8, 11, 11},    // F10
    {4, 3, 7, 10, 10, 9, 8, 8},    // F11
};

__global__ void __launch_bounds__(256) healpix_pad_kernel(
    const float* __restrict__ x, float* __restrict__ y)
{
    int gt   = blockIdx.x * blockDim.x + threadIdx.x;
    int w    = gt >> 5;
    int lane = gt & 31;
    if (w >= NWARPS) return;

    int P = w / NP;            // plane
    int r = w - P * NP;        // output row 0..129
    int F = (P >> 7) % 12;     // face
    int ty = F >> 2;           // 0=north, 1=equatorial, 2=south

    int inb  = P * PLANE_IN;
    float* outrow = y + (long)P * PLANE_OUT + r * NP;

    if (r >= 1 && r <= NN) {
        // ---------------- interior row (vectorized) ----------------
        int ir = r - 1;
        const float* inrow = x + inb + ir * NN;

        int lft_b = inb + (NBT[F][2] - F) * FACE_DELTA;
        int rgt_b = inb + (NBT[F][6] - F) * FACE_DELTA;

        float lh = 0.0f, rh = 0.0f;
        if (lane == 0)
            lh = x[(ty == 0) ? (lft_b + ir) : (lft_b + ir * NN + (NN - 1))];
        if (lane == 31)
            rh = x[(ty == 2) ? (rgt_b + (NN - 1) * NN + ir) : (rgt_b + ir * NN)];

        float4 f4 = *reinterpret_cast<const float4*>(inrow + 4 * lane);

        if ((r & 1) == 0) {
            // phase 0: aligned output chunks at cols [4k .. 4k+3]
            float s = (lane == 0) ? lh : inrow[4 * lane - 1];
            *reinterpret_cast<float4*>(outrow + 4 * lane) =
                make_float4(s, f4.x, f4.y, f4.z);
            if (lane == 31) {
                outrow[128] = f4.w;   // in[127]
                outrow[129] = rh;
            }
        } else {
            // phase 2: aligned output chunks at cols [4k+2 .. 4k+5]
            float s = (lane == 31) ? rh : inrow[4 * lane + 4];
            *reinterpret_cast<float4*>(outrow + 4 * lane + 2) =
                make_float4(f4.y, f4.z, f4.w, s);
            if (lane == 0) {
                outrow[0] = lh;
                outrow[1] = f4.x;     // in[0]
            }
        }
    } else if (r == 0) {
        // ---------------- top halo row ----------------
        int tbase = inb + (NBT[F][0] - F) * FACE_DELTA;
        #pragma unroll
        for (int j = lane; j < NP; j += 32) {
            float v;
            if (j == 0) {
                if (ty == 0) {
                    v = x[inb + (NBT[F][1] - F) * FACE_DELTA];             // tl[0,0]
                } else if (ty == 1) {
                    int lb = inb + (NBT[F][2] - F) * FACE_DELTA;
                    v = 0.5f * x[tbase + (NN - 1) * NN]                    // t[127,0]
                      + 0.5f * x[lb + (NN - 1)];                           // lft[0,127]
                } else {
                    v = x[inb + (NBT[F][1] - F) * FACE_DELTA
                          + (NN - 1) * NN + (NN - 1)];                     // tl[127,127]
                }
            } else if (j == NP - 1) {
                v = x[inb + (NBT[F][7] - F) * FACE_DELTA + (NN - 1) * NN]; // tr[127,0]
            } else {
                int jj = j - 1;
                v = (ty == 0) ? x[tbase + jj * NN]                         // t[jj,0]
                              : x[tbase + (NN - 1) * NN + jj];             // t[127,jj]
            }
            outrow[j] = v;
        }
    } else {
        // ---------------- bottom halo row (r == 129) ----------------
        int bbase = inb + (NBT[F][4] - F) * FACE_DELTA;
        #pragma unroll
        for (int j = lane; j < NP; j += 32) {
            float v;
            if (j == 0) {
                v = x[inb + (NBT[F][3] - F) * FACE_DELTA + (NN - 1)];      // bl[0,127]
            } else if (j == NP - 1) {
                if (ty == 0) {
                    v = x[inb + (NBT[F][5] - F) * FACE_DELTA];             // br[0,0]
                } else if (ty == 1) {
                    int rb = inb + (NBT[F][6] - F) * FACE_DELTA;
                    v = 0.5f * x[bbase + (NN - 1)]                         // b[0,127]
                      + 0.5f * x[rb + (NN - 1) * NN];                      // rgt[127,0]
                } else {
                    v = x[inb + (NBT[F][5] - F) * FACE_DELTA
                          + (NN - 1) * NN + (NN - 1)];                     // br[127,127]
                }
            } else {
                int jj = j - 1;
                v = (ty == 2) ? x[bbase + jj * NN + (NN - 1)]              // b[jj,127]
                              : x[bbase + jj];                             // b[0,jj]
            }
            outrow[j] = v;
        }
    }
}

extern "C" void kernel_launch(void* const* d_in, const int* in_sizes, int n_in,
                              void* d_out, int out_size)
{
    const float* x = (const float*)d_in[0];
    float* y = (float*)d_out;

    const int threads = 256;
    const int total_threads = NWARPS * 32;                 // 12,779,520
    const int blocks = (total_threads + threads - 1) / threads;  // 49,920
    healpix_pad_kernel<<<blocks, threads>>>(x, y);
}